// round 10
// baseline (speedup 1.0000x reference)
#include <cuda_runtime.h>
#include <cuda_bf16.h>
#include <cstdint>
#include <cstddef>

// Pairwise Euclidean distance, B=8192, K=256, D=3072, fp32.
// out[b,k] = sqrt(max(||x||^2 + ||c||^2 - 2 x.c, eps))
// Prepass: centers fp32->bf16 + csq. Main: bf16 mma.sync GEMM, 512 threads,
// two independent 256-thread k-parity pipelines (named barriers, 4-stage
// subrings). R10: conflict-free A STS.128 mapping + running pointers.

#define BB 8192
#define KK 256
#define DD 3072
#define BM 128
#define BN 128
#define BK 32
#define NT (DD / BK)            // 96 k-tiles
#define NTG (NT / 2)            // 48 per group
#define NTHREADS 512
#define EPS_F 1e-12f

#define ROW_B 80                // 32 bf16 + pad: ldmatrix conflict-free
#define TILE_B (128 * ROW_B)    // 10240
#define STAGE_B (2 * TILE_B)    // 20480 (A then B)
#define GSTEP (2 * STAGE_B)     // group-local stage stride
#define NSTAGE 8
#define OFF_XSQ  (NSTAGE * STAGE_B)          // 163840
#define OFF_CSQ  (OFF_XSQ + 512)
#define SMEM_BYTES (OFF_CSQ + 512)
#define STASH_STRIDE 132

__device__ __nv_bfloat16 g_cb[KK * DD];
__device__ float g_csq[KK];

static __device__ __forceinline__ uint32_t s2u(const void* p) {
    uint32_t a;
    asm("{.reg .u64 t; cvta.to.shared.u64 t, %1; cvt.u32.u64 %0, t;}"
        : "=r"(a) : "l"(p));
    return a;
}

#define LDSM_X4(r0, r1, r2, r3, a)                                            \
    asm volatile("ldmatrix.sync.aligned.m8n8.x4.shared.b16 {%0,%1,%2,%3}, [%4];" \
                 : "=r"(r0), "=r"(r1), "=r"(r2), "=r"(r3) : "r"(a))

#define MMA(acc, a, b0, b1)                                                   \
    asm volatile("mma.sync.aligned.m16n8k16.row.col.f32.bf16.bf16.f32 "       \
                 "{%0,%1,%2,%3}, {%4,%5,%6,%7}, {%8,%9}, {%0,%1,%2,%3};\n"    \
                 : "+f"((acc)[0]), "+f"((acc)[1]), "+f"((acc)[2]), "+f"((acc)[3]) \
                 : "r"((a)[0]), "r"((a)[1]), "r"((a)[2]), "r"((a)[3]),        \
                   "r"(b0), "r"(b1))

#define GBAR(id) asm volatile("bar.sync %0, 256;" :: "r"(id) : "memory")

// ---------------- prepass: centers fp32 -> bf16, csq ----------------
__global__ void __launch_bounds__(128, 8)
prep_c_kernel(const float* __restrict__ C)
{
    const int row = blockIdx.x;
    const float4* src = reinterpret_cast<const float4*>(C + (size_t)row * DD);
    uint2* dst = reinterpret_cast<uint2*>(g_cb + (size_t)row * DD);
    float s = 0.f;
    #pragma unroll
    for (int i = 0; i < 6; i++) {
        const int q = threadIdx.x + i * 128;
        float4 v = src[q];
        s += v.x * v.x + v.y * v.y + v.z * v.z + v.w * v.w;
        __nv_bfloat162 p0 = __float22bfloat162_rn(make_float2(v.x, v.y));
        __nv_bfloat162 p1 = __float22bfloat162_rn(make_float2(v.z, v.w));
        uint2 u;
        u.x = *reinterpret_cast<uint32_t*>(&p0);
        u.y = *reinterpret_cast<uint32_t*>(&p1);
        dst[q] = u;
    }
    #pragma unroll
    for (int o = 16; o > 0; o >>= 1)
        s += __shfl_xor_sync(0xFFFFFFFFu, s, o);
    __shared__ float red[4];
    if ((threadIdx.x & 31) == 0) red[threadIdx.x >> 5] = s;
    __syncthreads();
    if (threadIdx.x == 0)
        g_csq[row] = red[0] + red[1] + red[2] + red[3];
}

// ---------------- main GEMM ----------------
__global__ void __launch_bounds__(NTHREADS, 1)
rbf_dual_kernel(const float* __restrict__ X, float* __restrict__ out)
{
    extern __shared__ __align__(16) char smem[];
    const uint32_t sb = s2u(smem);
    const int tid  = threadIdx.x;
    const int wid  = tid >> 5;
    const int lane = tid & 31;
    const int bm = blockIdx.y;
    const int bn = blockIdx.x;

    const int g   = wid >> 3;          // k-parity group
    const int gt  = tid & 255;
    const int bar = g + 1;

    float* xsq_s = (float*)(smem + OFF_XSQ);
    float* csq_s = (float*)(smem + OFF_CSQ);
    if (tid < 128) {
        xsq_s[tid] = 0.f;
        csq_s[tid] = g_csq[bn * BN + tid];
    }
    __syncthreads();

    const uint32_t sbg = sb + (uint32_t)g * STAGE_B;

    // ---- A producer: conflict-free mapping ----
    // r = (gt&7) + 8*(gt>>5): lanes 0-7 of each warp hit 8 DISTINCT rows at the
    // same 16B granule c8 -> STS.128 store phases are bank-conflict-free
    // (starts 20r mod 32 all distinct, spacing 4 banks).
    const int arow = (gt & 7) + 8 * (gt >> 5);       // 0..63
    const int c8   = (gt >> 3) & 3;                  // 16B bf16 granule = 8 floats
    const float4* pA0 = reinterpret_cast<const float4*>(
        X + (size_t)(bm * BM + arow) * DD + g * BK + c8 * 8);
    const float4* pA1 = reinterpret_cast<const float4*>(
        X + (size_t)(bm * BM + arow + 64) * DD + g * BK + c8 * 8);
    const uint32_t adst0 = (uint32_t)arow * ROW_B + (uint32_t)c8 * 16;
    const uint32_t adst1 = adst0 + (uint32_t)(64 * ROW_B);
    float4 ra[4];
    float xs0 = 0.f, xs1 = 0.f;

    auto ldgA = [&]() {
        ra[0] = pA0[0]; ra[1] = pA0[1];
        ra[2] = pA1[0]; ra[3] = pA1[1];
        pA0 += 16; pA1 += 16;          // 64 floats = 2 global k-tiles
    };
    auto stsA = [&](int i) {
        const uint32_t base = sbg + (uint32_t)(i & 3) * GSTEP;
        xs0 += ra[0].x * ra[0].x + ra[0].y * ra[0].y + ra[0].z * ra[0].z + ra[0].w * ra[0].w
             + ra[1].x * ra[1].x + ra[1].y * ra[1].y + ra[1].z * ra[1].z + ra[1].w * ra[1].w;
        xs1 += ra[2].x * ra[2].x + ra[2].y * ra[2].y + ra[2].z * ra[2].z + ra[2].w * ra[2].w
             + ra[3].x * ra[3].x + ra[3].y * ra[3].y + ra[3].z * ra[3].z + ra[3].w * ra[3].w;
        __nv_bfloat162 p0 = __float22bfloat162_rn(make_float2(ra[0].x, ra[0].y));
        __nv_bfloat162 p1 = __float22bfloat162_rn(make_float2(ra[0].z, ra[0].w));
        __nv_bfloat162 p2 = __float22bfloat162_rn(make_float2(ra[1].x, ra[1].y));
        __nv_bfloat162 p3 = __float22bfloat162_rn(make_float2(ra[1].z, ra[1].w));
        asm volatile("st.shared.v4.b32 [%0], {%1,%2,%3,%4};"
                     :: "r"(base + adst0),
                        "r"(*reinterpret_cast<uint32_t*>(&p0)),
                        "r"(*reinterpret_cast<uint32_t*>(&p1)),
                        "r"(*reinterpret_cast<uint32_t*>(&p2)),
                        "r"(*reinterpret_cast<uint32_t*>(&p3)) : "memory");
        p0 = __float22bfloat162_rn(make_float2(ra[2].x, ra[2].y));
        p1 = __float22bfloat162_rn(make_float2(ra[2].z, ra[2].w));
        p2 = __float22bfloat162_rn(make_float2(ra[3].x, ra[3].y));
        p3 = __float22bfloat162_rn(make_float2(ra[3].z, ra[3].w));
        asm volatile("st.shared.v4.b32 [%0], {%1,%2,%3,%4};"
                     :: "r"(base + adst1),
                        "r"(*reinterpret_cast<uint32_t*>(&p0)),
                        "r"(*reinterpret_cast<uint32_t*>(&p1)),
                        "r"(*reinterpret_cast<uint32_t*>(&p2)),
                        "r"(*reinterpret_cast<uint32_t*>(&p3)) : "memory");
    };

    // ---- B producer: cp.async, running pointers ----
    const int br = gt >> 2;            // 0..63; rows br, br+64
    const int bc = gt & 3;             // 16B chunk
    const __nv_bfloat16* pB0 = g_cb + (size_t)(bn * BN + br) * DD + g * BK + bc * 8;
    const __nv_bfloat16* pB1 = pB0 + (size_t)64 * DD;
    const uint32_t bdst = (uint32_t)br * ROW_B + (uint32_t)bc * 16 + (uint32_t)TILE_B;
    auto cpB = [&](int i) {
        const uint32_t base = sbg + (uint32_t)(i & 3) * GSTEP + bdst;
        asm volatile("cp.async.cg.shared.global [%0], [%1], 16;"
                     :: "r"(base), "l"(pB0) : "memory");
        asm volatile("cp.async.cg.shared.global [%0], [%1], 16;"
                     :: "r"(base + (uint32_t)(64 * ROW_B)), "l"(pB1) : "memory");
        asm volatile("cp.async.commit_group;" ::: "memory");
        pB0 += 64; pB1 += 64;          // 2 global k-tiles
    };

    // ---- compute mapping: per group 4(M)x2(N), warp tile 32x64 ----
    const int w8 = wid & 7;
    const int wm = w8 & 3;
    const int wn = w8 >> 2;
    const int fr = lane >> 2;
    const int fc = (lane & 3) * 2;
    const int lg = lane >> 3;
    const int ri = lane & 7;
    const uint32_t lm_off = (uint32_t)(((lg & 1) * 8 + ri) * ROW_B + (lg >> 1) * 16);
    const uint32_t a_off = (uint32_t)(wm * 32 * ROW_B) + lm_off;
    const uint32_t b_off = (uint32_t)(wn * 64 * ROW_B) + lm_off + (uint32_t)TILE_B;

    float acc[2][8][4];
    #pragma unroll
    for (int i = 0; i < 2; i++)
        #pragma unroll
        for (int j = 0; j < 8; j++)
            #pragma unroll
            for (int q = 0; q < 4; q++) acc[i][j][q] = 0.f;

    // ---- prologue ----
    ldgA();
    cpB(0);
    stsA(0);
    ldgA();
    cpB(1);
    asm volatile("cp.async.wait_group 1;" ::: "memory");
    GBAR(bar);

    // ---- mainloop ----
    #pragma unroll 1
    for (int i = 0; i < NTG; i++) {
        const uint32_t st = sbg + (uint32_t)(i & 3) * GSTEP;
        const uint32_t stA = st + a_off;
        const uint32_t stB = st + b_off;

        #pragma unroll
        for (int ks = 0; ks < 2; ks++) {
            const uint32_t kof = (uint32_t)ks * 32;
            uint32_t a[2][4], b[4][4];
            LDSM_X4(a[0][0], a[0][1], a[0][2], a[0][3], stA + kof);
            LDSM_X4(a[1][0], a[1][1], a[1][2], a[1][3], stA + kof + 16 * ROW_B);
            LDSM_X4(b[0][0], b[0][1], b[0][2], b[0][3], stB + kof);
            LDSM_X4(b[1][0], b[1][1], b[1][2], b[1][3], stB + kof + 16 * ROW_B);
            LDSM_X4(b[2][0], b[2][1], b[2][2], b[2][3], stB + kof + 32 * ROW_B);
            LDSM_X4(b[3][0], b[3][1], b[3][2], b[3][3], stB + kof + 48 * ROW_B);
            #pragma unroll
            for (int im = 0; im < 2; im++) {
                MMA(acc[im][0], a[im], b[0][0], b[0][2]);
                MMA(acc[im][1], a[im], b[0][1], b[0][3]);
                MMA(acc[im][2], a[im], b[1][0], b[1][2]);
                MMA(acc[im][3], a[im], b[1][1], b[1][3]);
                MMA(acc[im][4], a[im], b[2][0], b[2][2]);
                MMA(acc[im][5], a[im], b[2][1], b[2][3]);
                MMA(acc[im][6], a[im], b[3][0], b[3][2]);
                MMA(acc[im][7], a[im], b[3][1], b[3][3]);
            }
        }

        if (i + 1 < NTG) {
            stsA(i + 1);
            if (i + 2 < NTG) {
                ldgA();
                cpB(i + 2);
                asm volatile("cp.async.wait_group 1;" ::: "memory");
            } else {
                asm volatile("cp.async.wait_group 0;" ::: "memory");
            }
        }
        GBAR(bar);
    }

    // ---- norms (4-way contention max) ----
    atomicAdd(&xsq_s[arow], xs0);
    atomicAdd(&xsq_s[arow + 64], xs1);
    __syncthreads();

    // ---- split-k merge + fused epilogue ----
    float* stash = (float*)smem;
    if (g == 1) {
        #pragma unroll
        for (int im = 0; im < 2; im++)
            #pragma unroll
            for (int hf = 0; hf < 2; hf++) {
                const int row = wm * 32 + im * 16 + hf * 8 + fr;
                #pragma unroll
                for (int j = 0; j < 8; j++) {
                    const int col = wn * 64 + j * 8 + fc;
                    *reinterpret_cast<float2*>(&stash[row * STASH_STRIDE + col]) =
                        make_float2(acc[im][j][hf * 2], acc[im][j][hf * 2 + 1]);
                }
            }
    }
    __syncthreads();
    if (g == 0) {
        #pragma unroll
        for (int im = 0; im < 2; im++)
            #pragma unroll
            for (int hf = 0; hf < 2; hf++) {
                const int row = wm * 32 + im * 16 + hf * 8 + fr;
                const float xq = xsq_s[row];
                float* orow = out + ((size_t)bm * BM + row) * KK + bn * BN;
                #pragma unroll
                for (int j = 0; j < 8; j++) {
                    const int col = wn * 64 + j * 8 + fc;
                    const float2 o = *reinterpret_cast<const float2*>(
                        &stash[row * STASH_STRIDE + col]);
                    const float cr0 = acc[im][j][hf * 2] + o.x;
                    const float cr1 = acc[im][j][hf * 2 + 1] + o.y;
                    const float d0 = sqrtf(fmaxf(xq + csq_s[col] - 2.f * cr0, EPS_F));
                    const float d1 = sqrtf(fmaxf(xq + csq_s[col + 1] - 2.f * cr1, EPS_F));
                    *reinterpret_cast<float2*>(orow + col) = make_float2(d0, d1);
                }
            }
    }
}

extern "C" void kernel_launch(void* const* d_in, const int* in_sizes, int n_in,
                              void* d_out, int out_size)
{
    const float* X = (const float*)d_in[0];
    const float* C = (const float*)d_in[1];
    float* out = (float*)d_out;

    prep_c_kernel<<<KK, 128>>>(C);

    cudaFuncSetAttribute(rbf_dual_kernel,
                         cudaFuncAttributeMaxDynamicSharedMemorySize, SMEM_BYTES);
    dim3 grid(KK / BN, BB / BM);
    rbf_dual_kernel<<<grid, NTHREADS, SMEM_BYTES>>>(X, out);
}

// round 11
// speedup vs baseline: 1.3134x; 1.3134x over previous
#include <cuda_runtime.h>
#include <cuda_bf16.h>
#include <cstdint>
#include <cstddef>

// Pairwise Euclidean distance, B=8192, K=256, D=3072, fp32.
// out[b,k] = sqrt(max(||x||^2 + ||c||^2 - 2 x.c, eps))
// R11 = R8 (proven 64us) + running pointers + crossbar-op spreading + group desync.
// Two independent 256-thread k-parity pipelines, named barriers, 4-stage subrings.

#define BB 8192
#define KK 256
#define DD 3072
#define BM 128
#define BN 128
#define BK 32
#define NT (DD / BK)            // 96 k-tiles
#define NTG (NT / 2)            // 48 per group
#define NTHREADS 512
#define EPS_F 1e-12f

#define ROW_B 80                // 32 bf16 + pad: ldmatrix conflict-free
#define TILE_B (128 * ROW_B)    // 10240
#define STAGE_B (2 * TILE_B)    // 20480 (A then B)
#define GSTEP (2 * STAGE_B)
#define NSTAGE 8
#define OFF_XSQ  (NSTAGE * STAGE_B)
#define OFF_CSQ  (OFF_XSQ + 512)
#define SMEM_BYTES (OFF_CSQ + 512)
#define STASH_STRIDE 132

__device__ __nv_bfloat16 g_cb[KK * DD];
__device__ float g_csq[KK];

static __device__ __forceinline__ uint32_t s2u(const void* p) {
    uint32_t a;
    asm("{.reg .u64 t; cvta.to.shared.u64 t, %1; cvt.u32.u64 %0, t;}"
        : "=r"(a) : "l"(p));
    return a;
}

#define LDSM_X4(r0, r1, r2, r3, a)                                            \
    asm volatile("ldmatrix.sync.aligned.m8n8.x4.shared.b16 {%0,%1,%2,%3}, [%4];" \
                 : "=r"(r0), "=r"(r1), "=r"(r2), "=r"(r3) : "r"(a))

#define MMA(acc, a, b0, b1)                                                   \
    asm volatile("mma.sync.aligned.m16n8k16.row.col.f32.bf16.bf16.f32 "       \
                 "{%0,%1,%2,%3}, {%4,%5,%6,%7}, {%8,%9}, {%0,%1,%2,%3};\n"    \
                 : "+f"((acc)[0]), "+f"((acc)[1]), "+f"((acc)[2]), "+f"((acc)[3]) \
                 : "r"((a)[0]), "r"((a)[1]), "r"((a)[2]), "r"((a)[3]),        \
                   "r"(b0), "r"(b1))

#define GBAR(id) asm volatile("bar.sync %0, 256;" :: "r"(id) : "memory")

// ---------------- prepass: centers fp32 -> bf16, csq ----------------
__global__ void __launch_bounds__(128, 8)
prep_c_kernel(const float* __restrict__ C)
{
    const int row = blockIdx.x;
    const float4* src = reinterpret_cast<const float4*>(C + (size_t)row * DD);
    uint2* dst = reinterpret_cast<uint2*>(g_cb + (size_t)row * DD);
    float s = 0.f;
    #pragma unroll
    for (int i = 0; i < 6; i++) {
        const int q = threadIdx.x + i * 128;
        float4 v = src[q];
        s += v.x * v.x + v.y * v.y + v.z * v.z + v.w * v.w;
        __nv_bfloat162 p0 = __float22bfloat162_rn(make_float2(v.x, v.y));
        __nv_bfloat162 p1 = __float22bfloat162_rn(make_float2(v.z, v.w));
        uint2 u;
        u.x = *reinterpret_cast<uint32_t*>(&p0);
        u.y = *reinterpret_cast<uint32_t*>(&p1);
        dst[q] = u;
    }
    #pragma unroll
    for (int o = 16; o > 0; o >>= 1)
        s += __shfl_xor_sync(0xFFFFFFFFu, s, o);
    __shared__ float red[4];
    if ((threadIdx.x & 31) == 0) red[threadIdx.x >> 5] = s;
    __syncthreads();
    if (threadIdx.x == 0)
        g_csq[row] = red[0] + red[1] + red[2] + red[3];
}

// ---------------- main GEMM ----------------
__global__ void __launch_bounds__(NTHREADS, 1)
rbf_dual_kernel(const float* __restrict__ X, float* __restrict__ out)
{
    extern __shared__ __align__(16) char smem[];
    const uint32_t sb = s2u(smem);
    const int tid  = threadIdx.x;
    const int wid  = tid >> 5;
    const int lane = tid & 31;
    const int bm = blockIdx.y;
    const int bn = blockIdx.x;

    const int g   = wid >> 3;
    const int gt  = tid & 255;
    const int bar = g + 1;

    float* xsq_s = (float*)(smem + OFF_XSQ);
    float* csq_s = (float*)(smem + OFF_CSQ);
    if (tid < 128) {
        xsq_s[tid] = 0.f;
        csq_s[tid] = g_csq[bn * BN + tid];
    }
    __syncthreads();

    const uint32_t sbg = sb + (uint32_t)g * STAGE_B;

    // ---- A producer: R8 mapping (quarter-warp = 1 line), running pointers ----
    const int lr = gt >> 3;            // 0..31; rows lr + 32p
    const int c4 = gt & 7;             // 16B granule -> 128B contiguous per 8 lanes
    const float4* pA0 = reinterpret_cast<const float4*>(
        X + (size_t)(bm * BM + lr) * DD + g * BK) + c4;
    const float4* pA1 = pA0 + 32 * (DD / 4);
    const float4* pA2 = pA0 + 64 * (DD / 4);
    const float4* pA3 = pA0 + 96 * (DD / 4);
    const uint32_t adst = (uint32_t)lr * ROW_B + (uint32_t)c4 * 8;
    float4 ra[4];
    float xs[4] = {0.f, 0.f, 0.f, 0.f};

    auto ldgA = [&]() {
        ra[0] = *pA0; ra[1] = *pA1; ra[2] = *pA2; ra[3] = *pA3;
        pA0 += 16; pA1 += 16; pA2 += 16; pA3 += 16;   // 64 floats = 2 k-tiles
    };
    auto stsA = [&](int i) {
        const uint32_t base = sbg + (uint32_t)(i & 3) * GSTEP + adst;
        #pragma unroll
        for (int p = 0; p < 4; p++) {
            float4 v = ra[p];
            xs[p] += v.x * v.x + v.y * v.y + v.z * v.z + v.w * v.w;
            __nv_bfloat162 q0 = __float22bfloat162_rn(make_float2(v.x, v.y));
            __nv_bfloat162 q1 = __float22bfloat162_rn(make_float2(v.z, v.w));
            asm volatile("st.shared.v2.b32 [%0], {%1,%2};"
                         :: "r"(base + (uint32_t)(p * 32 * ROW_B)),
                            "r"(*reinterpret_cast<uint32_t*>(&q0)),
                            "r"(*reinterpret_cast<uint32_t*>(&q1)) : "memory");
        }
    };

    // ---- B producer: cp.async, running pointers ----
    const int br = gt >> 2;            // rows br, br+64
    const int bc = gt & 3;
    const __nv_bfloat16* pB0 = g_cb + (size_t)(bn * BN + br) * DD + g * BK + bc * 8;
    const __nv_bfloat16* pB1 = pB0 + (size_t)64 * DD;
    const uint32_t bdst = (uint32_t)br * ROW_B + (uint32_t)bc * 16 + (uint32_t)TILE_B;
    auto cpB = [&](int i) {
        const uint32_t base = sbg + (uint32_t)(i & 3) * GSTEP + bdst;
        asm volatile("cp.async.cg.shared.global [%0], [%1], 16;"
                     :: "r"(base), "l"(pB0) : "memory");
        asm volatile("cp.async.cg.shared.global [%0], [%1], 16;"
                     :: "r"(base + (uint32_t)(64 * ROW_B)), "l"(pB1) : "memory");
        asm volatile("cp.async.commit_group;" ::: "memory");
        pB0 += 64; pB1 += 64;
    };

    // ---- compute mapping: per group 4(M)x2(N), warp tile 32x64 ----
    const int w8 = wid & 7;
    const int wm = w8 & 3;
    const int wn = w8 >> 2;
    const int fr = lane >> 2;
    const int fc = (lane & 3) * 2;
    const int lg = lane >> 3;
    const int ri = lane & 7;
    const uint32_t lm_off = (uint32_t)(((lg & 1) * 8 + ri) * ROW_B + (lg >> 1) * 16);
    const uint32_t a_off = (uint32_t)(wm * 32 * ROW_B) + lm_off;
    const uint32_t b_off = (uint32_t)(wn * 64 * ROW_B) + lm_off + (uint32_t)TILE_B;

    float acc[2][8][4];
    #pragma unroll
    for (int i = 0; i < 2; i++)
        #pragma unroll
        for (int j = 0; j < 8; j++)
            #pragma unroll
            for (int q = 0; q < 4; q++) acc[i][j][q] = 0.f;

    // ---- desync: group 1 starts ~600 cyc late so pipelines anti-phase ----
    if (g == 1) {
        const unsigned long long t0 = clock64();
        while (clock64() - t0 < 600) { }
    }

    // ---- prologue ----
    ldgA();
    cpB(0);
    stsA(0);
    ldgA();
    cpB(1);
    asm volatile("cp.async.wait_group 1;" ::: "memory");
    GBAR(bar);

    // ---- mainloop: crossbar ops spread between the two MMA half-phases ----
    #pragma unroll 1
    for (int i = 0; i < NTG; i++) {
        const uint32_t st = sbg + (uint32_t)(i & 3) * GSTEP;
        const uint32_t stA = st + a_off;
        const uint32_t stB = st + b_off;

        // ks = 0
        {
            uint32_t a[2][4], b[4][4];
            LDSM_X4(a[0][0], a[0][1], a[0][2], a[0][3], stA);
            LDSM_X4(a[1][0], a[1][1], a[1][2], a[1][3], stA + 16 * ROW_B);
            LDSM_X4(b[0][0], b[0][1], b[0][2], b[0][3], stB);
            LDSM_X4(b[1][0], b[1][1], b[1][2], b[1][3], stB + 16 * ROW_B);
            LDSM_X4(b[2][0], b[2][1], b[2][2], b[2][3], stB + 32 * ROW_B);
            LDSM_X4(b[3][0], b[3][1], b[3][2], b[3][3], stB + 48 * ROW_B);
            #pragma unroll
            for (int im = 0; im < 2; im++) {
                MMA(acc[im][0], a[im], b[0][0], b[0][2]);
                MMA(acc[im][1], a[im], b[0][1], b[0][3]);
                MMA(acc[im][2], a[im], b[1][0], b[1][2]);
                MMA(acc[im][3], a[im], b[1][1], b[1][3]);
                MMA(acc[im][4], a[im], b[2][0], b[2][2]);
                MMA(acc[im][5], a[im], b[2][1], b[2][3]);
                MMA(acc[im][6], a[im], b[3][0], b[3][2]);
                MMA(acc[im][7], a[im], b[3][1], b[3][3]);
            }
        }

        // producer work overlaps tensor-pipe drain of ks0 MMAs
        if (i + 1 < NTG) {
            stsA(i + 1);
            if (i + 2 < NTG) cpB(i + 2);
        }

        // ks = 1
        {
            uint32_t a[2][4], b[4][4];
            LDSM_X4(a[0][0], a[0][1], a[0][2], a[0][3], stA + 32);
            LDSM_X4(a[1][0], a[1][1], a[1][2], a[1][3], stA + 32 + 16 * ROW_B);
            LDSM_X4(b[0][0], b[0][1], b[0][2], b[0][3], stB + 32);
            LDSM_X4(b[1][0], b[1][1], b[1][2], b[1][3], stB + 32 + 16 * ROW_B);
            LDSM_X4(b[2][0], b[2][1], b[2][2], b[2][3], stB + 32 + 32 * ROW_B);
            LDSM_X4(b[3][0], b[3][1], b[3][2], b[3][3], stB + 32 + 48 * ROW_B);
            #pragma unroll
            for (int im = 0; im < 2; im++) {
                MMA(acc[im][0], a[im], b[0][0], b[0][2]);
                MMA(acc[im][1], a[im], b[0][1], b[0][3]);
                MMA(acc[im][2], a[im], b[1][0], b[1][2]);
                MMA(acc[im][3], a[im], b[1][1], b[1][3]);
                MMA(acc[im][4], a[im], b[2][0], b[2][2]);
                MMA(acc[im][5], a[im], b[2][1], b[2][3]);
                MMA(acc[im][6], a[im], b[3][0], b[3][2]);
                MMA(acc[im][7], a[im], b[3][1], b[3][3]);
            }
        }

        if (i + 2 < NTG) {
            ldgA();
            asm volatile("cp.async.wait_group 1;" ::: "memory");
        } else {
            asm volatile("cp.async.wait_group 0;" ::: "memory");
        }
        GBAR(bar);
    }

    // ---- norms ----
    #pragma unroll
    for (int p = 0; p < 4; p++)
        atomicAdd(&xsq_s[p * 32 + lr], xs[p]);
    __syncthreads();

    // ---- split-k merge + fused epilogue ----
    float* stash = (float*)smem;
    if (g == 1) {
        #pragma unroll
        for (int im = 0; im < 2; im++)
            #pragma unroll
            for (int hf = 0; hf < 2; hf++) {
                const int row = wm * 32 + im * 16 + hf * 8 + fr;
                #pragma unroll
                for (int j = 0; j < 8; j++) {
                    const int col = wn * 64 + j * 8 + fc;
                    *reinterpret_cast<float2*>(&stash[row * STASH_STRIDE + col]) =
                        make_float2(acc[im][j][hf * 2], acc[im][j][hf * 2 + 1]);
                }
            }
    }
    __syncthreads();
    if (g == 0) {
        #pragma unroll
        for (int im = 0; im < 2; im++)
            #pragma unroll
            for (int hf = 0; hf < 2; hf++) {
                const int row = wm * 32 + im * 16 + hf * 8 + fr;
                const float xq = xsq_s[row];
                float* orow = out + ((size_t)bm * BM + row) * KK + bn * BN;
                #pragma unroll
                for (int j = 0; j < 8; j++) {
                    const int col = wn * 64 + j * 8 + fc;
                    const float2 o = *reinterpret_cast<const float2*>(
                        &stash[row * STASH_STRIDE + col]);
                    const float cr0 = acc[im][j][hf * 2] + o.x;
                    const float cr1 = acc[im][j][hf * 2 + 1] + o.y;
                    const float d0 = sqrtf(fmaxf(xq + csq_s[col] - 2.f * cr0, EPS_F));
                    const float d1 = sqrtf(fmaxf(xq + csq_s[col + 1] - 2.f * cr1, EPS_F));
                    *reinterpret_cast<float2*>(orow + col) = make_float2(d0, d1);
                }
            }
    }
}

extern "C" void kernel_launch(void* const* d_in, const int* in_sizes, int n_in,
                              void* d_out, int out_size)
{
    const float* X = (const float*)d_in[0];
    const float* C = (const float*)d_in[1];
    float* out = (float*)d_out;

    prep_c_kernel<<<KK, 128>>>(C);

    cudaFuncSetAttribute(rbf_dual_kernel,
                         cudaFuncAttributeMaxDynamicSharedMemorySize, SMEM_BYTES);
    dim3 grid(KK / BN, BB / BM);
    rbf_dual_kernel<<<grid, NTHREADS, SMEM_BYTES>>>(X, out);
}